// round 13
// baseline (speedup 1.0000x reference)
#include <cuda_runtime.h>
#include <cuda_fp16.h>
#include <math_constants.h>
#include <cstdint>

#define N_PTS 16384
#define C_DIM 64
#define K_NN 16
#define SPLIT 8
#define SEG (N_PTS / SPLIT)
#define K_SEL 18
#define K_CAND (SPLIT * K_SEL)   // 144

__device__ float g_norms[N_PTS];
__device__ __half g_xh[N_PTS * C_DIM];
__device__ int g_pi[N_PTS * K_CAND];
__device__ int g_knn[N_PTS * K_NN];

// ---------------------------------------------------------------------------
// Kernel 0: norms + fp16 copy of x
// ---------------------------------------------------------------------------
__global__ __launch_bounds__(256) void prep_kernel(const float* __restrict__ x) {
    int i = blockIdx.x * 256 + threadIdx.x;
    const float4* xv = (const float4*)(x + (size_t)i * C_DIM);
    __half2* oh = (__half2*)(g_xh + (size_t)i * C_DIM);
    float s = 0.f;
#pragma unroll
    for (int d = 0; d < 16; ++d) {
        float4 v = xv[d];
        s += v.x * v.x + v.y * v.y + v.z * v.z + v.w * v.w;
        oh[2 * d]     = __floats2half2_rn(v.x, v.y);
        oh[2 * d + 1] = __floats2half2_rn(v.z, v.w);
    }
    g_norms[i] = s;
}

// ---------------------------------------------------------------------------
// Kernel 1: fp16 screen with packed u32 keys; top-18 per split.
// grid (128, 8) = 1024 CTAs x 128 thr; 7 CTAs/SM -> all co-resident.
// ---------------------------------------------------------------------------
#define QT 128
#define JT 128

__global__ __launch_bounds__(128, 7) void screen_kernel() {
    __shared__ __half sc[JT * C_DIM];   // 16 KB candidate tile
    __shared__ float sn[JT];

    int t = threadIdx.x;
    int q = blockIdx.x * QT + t;
    int s0 = blockIdx.y;

    __half2 xq[32];
    {
        const uint4* xv = (const uint4*)(g_xh + (size_t)q * C_DIM);
#pragma unroll
        for (int d = 0; d < 8; ++d) *(uint4*)&xq[4 * d] = xv[d];
    }
    float nq = g_norms[q];

    unsigned bd[K_SEL];
#pragma unroll
    for (int s = 0; s < K_SEL; ++s) bd[s] = 0xFFFFFFFFu;

    int jbeg = s0 * SEG, jend = jbeg + SEG;
    for (int jt = jbeg; jt < jend; jt += JT) {
        __syncthreads();
        const uint4* src = (const uint4*)(g_xh + (size_t)jt * C_DIM);
        uint4* dst = (uint4*)sc;
#pragma unroll
        for (int i = 0; i < 8; ++i) dst[t + i * 128] = src[t + i * 128];
        sn[t] = g_norms[jt + t];
        __syncthreads();

#pragma unroll 1
        for (int j = 0; j < JT; ++j) {
            const uint4* cr = (const uint4*)(sc + j * C_DIM);
            __half2 a0 = __float2half2_rn(0.f);
            __half2 a1 = a0, a2 = a0, a3 = a0;
#pragma unroll
            for (int d = 0; d < 8; ++d) {
                uint4 v = cr[d];                      // 4 half2, broadcast
                const __half2* cc = (const __half2*)&v;
                a0 = __hfma2(xq[4 * d],     cc[0], a0);
                a1 = __hfma2(xq[4 * d + 1], cc[1], a1);
                a2 = __hfma2(xq[4 * d + 2], cc[2], a2);
                a3 = __hfma2(xq[4 * d + 3], cc[3], a3);
            }
            __half2 h = __hadd2(__hadd2(a0, a1), __hadd2(a2, a3));
            float dot = __low2float(h) + __high2float(h);
            float m = fmaf(-2.f, dot, nq + sn[j]);
            unsigned key = ((unsigned)__half_as_ushort(__float2half_rn(m)) << 16)
                         | (unsigned)(jt + j);
            if (key < bd[K_SEL - 1]) {
                unsigned cur = key;
#pragma unroll
                for (int s = 0; s < K_SEL; ++s) {
                    unsigned lo = min(bd[s], cur);
                    cur = max(bd[s], cur);
                    bd[s] = lo;
                }
            }
        }
    }

    int lb = q * K_CAND + s0 * K_SEL;
#pragma unroll
    for (int s = 0; s < K_SEL; ++s) g_pi[lb + s] = (int)(bd[s] & 0xFFFFu);
}

// ---------------------------------------------------------------------------
// Kernel 2: exact fp32 rerank of 144 candidates -> top-16 set (warp/query)
// ---------------------------------------------------------------------------
__global__ __launch_bounds__(256) void rerank_kernel(const float* __restrict__ x) {
    int w = threadIdx.x >> 5, lane = threadIdx.x & 31;
    int q = blockIdx.x * 8 + w;
    const float4* xq = (const float4*)(x + (size_t)q * C_DIM);

    float dv[5]; int ci[5];
#pragma unroll
    for (int s = 0; s < 5; ++s) {
        int i = s * 32 + lane;
        int c = (i < K_CAND) ? g_pi[q * K_CAND + i] : q;
        if (c != q && i < K_CAND) {
            const float4* xc = (const float4*)(x + (size_t)c * C_DIM);
            float a0 = 0.f, a1 = 0.f, a2 = 0.f, a3 = 0.f;
#pragma unroll
            for (int d = 0; d < 16; ++d) {
                float4 u = xq[d], v = xc[d];
                a0 = fmaf(u.x, v.x, a0);
                a1 = fmaf(u.y, v.y, a1);
                a2 = fmaf(u.z, v.z, a2);
                a3 = fmaf(u.w, v.w, a3);
            }
            float dot = (a0 + a1) + (a2 + a3);
            dv[s] = g_norms[c] - 2.f * dot;     // nq const per q: rank-safe
            ci[s] = c;
        } else { dv[s] = CUDART_INF_F; ci[s] = -1; }
    }

#pragma unroll 1
    for (int s = 0; s < K_NN; ++s) {
        float m = dv[0]; int idx = ci[0], key = lane;
#pragma unroll
        for (int u = 1; u < 5; ++u)
            if (dv[u] < m) { m = dv[u]; idx = ci[u]; key = u * 32 + lane; }
#pragma unroll
        for (int off = 16; off > 0; off >>= 1) {
            float om = __shfl_xor_sync(0xffffffffu, m, off);
            int   oi = __shfl_xor_sync(0xffffffffu, idx, off);
            int   ok = __shfl_xor_sync(0xffffffffu, key, off);
            if (om < m || (om == m && ok < key)) { m = om; idx = oi; key = ok; }
        }
        if ((key & 31) == lane) {
            int slot = key >> 5;
            if (slot == 0) dv[0] = CUDART_INF_F;
            else if (slot == 1) dv[1] = CUDART_INF_F;
            else if (slot == 2) dv[2] = CUDART_INF_F;
            else if (slot == 3) dv[3] = CUDART_INF_F;
            else dv[4] = CUDART_INF_F;
        }
        if (lane == 0) g_knn[q * K_NN + s] = idx;
    }
}

// ---------------------------------------------------------------------------
// Kernel 3: factored edge-MLP, 2 CTAs/SM.
// base = b + x_i @ W_top  with W_top read from GLOBAL (L1/L2-resident, read
// once per query). Only W_bottom (64x256) lives in smem -> 98 KB total.
// Neighbor tile = 4 (fits 128 regs for 2-CTA residency).
// ---------------------------------------------------------------------------
#define MLP_SMEM_FLOATS (16384 + 8 * 1088)   // W_bottom + 8 x (64 + 16*64)

__global__ __launch_bounds__(256, 2) void mlp_kernel(const float* __restrict__ x,
                                                     const float* __restrict__ W,
                                                     const float* __restrict__ b,
                                                     float* __restrict__ y) {
    extern __shared__ float fsm[];
    float* sW    = fsm;                 // W rows 64..127 (64 x 256)
    float* sfeat = fsm + 16384;

    int tid  = threadIdx.x;
    int warp = tid >> 5;
    int lane = tid & 31;

    {
        const float4* Wv = (const float4*)W;    // W_bottom starts at float4 4096
        float4* sWv = (float4*)sW;
        for (int i = tid; i < 4096; i += 256) sWv[i] = Wv[4096 + i];
    }
    float bb[8];
#pragma unroll
    for (int k = 0; k < 8; ++k) bb[k] = b[lane * 8 + k];
    __syncthreads();

    float* f = sfeat + warp * 1088;           // [0:64]=x_i, then 16 x 64 diffs
    const float4* f4  = (const float4*)f;
    const float4* sW4 = (const float4*)sW;
    const float4* Wt  = (const float4*)W;     // W_top, global (L1-resident)

    for (int qg = blockIdx.x; qg < N_PTS / 8; qg += gridDim.x) {
        int q = qg * 8 + warp;

        float xi0 = x[(size_t)q * 64 + lane];
        float xi1 = x[(size_t)q * 64 + 32 + lane];
        f[lane]      = xi0;
        f[32 + lane] = xi1;
#pragma unroll 4
        for (int n = 0; n < 16; ++n) {
            int j = g_knn[q * 16 + n];
            float v0 = x[(size_t)j * 64 + lane];
            float v1 = x[(size_t)j * 64 + 32 + lane];
            f[64 + n * 64 + lane]      = v0 - xi0;
            f[64 + n * 64 + 32 + lane] = v1 - xi1;
        }
        __syncwarp();

        // neighbor-invariant base: bb + x_i @ W_top (W_top from global)
        float base[8];
#pragma unroll
        for (int k = 0; k < 8; ++k) base[k] = bb[k];
#pragma unroll 2
        for (int d = 0; d < 64; d += 4) {
            float4 fe4 = f4[d >> 2];                         // broadcast
#pragma unroll
            for (int dd = 0; dd < 4; ++dd) {
                float4 w0 = Wt[(d + dd) * 64 + lane * 2];
                float4 w1 = Wt[(d + dd) * 64 + lane * 2 + 1];
                float fe = (dd == 0) ? fe4.x : (dd == 1) ? fe4.y
                         : (dd == 2) ? fe4.z : fe4.w;
                base[0] = fmaf(fe, w0.x, base[0]);
                base[1] = fmaf(fe, w0.y, base[1]);
                base[2] = fmaf(fe, w0.z, base[2]);
                base[3] = fmaf(fe, w0.w, base[3]);
                base[4] = fmaf(fe, w1.x, base[4]);
                base[5] = fmaf(fe, w1.y, base[5]);
                base[6] = fmaf(fe, w1.z, base[6]);
                base[7] = fmaf(fe, w1.w, base[7]);
            }
        }

        float vmax[8];
#pragma unroll
        for (int k = 0; k < 8; ++k) vmax[k] = 0.f;           // relu >= 0

#pragma unroll 1
        for (int ch = 0; ch < 4; ++ch) {                     // 4 neighbors/chunk
            float acc[4][8];
#pragma unroll
            for (int n = 0; n < 4; ++n)
#pragma unroll
                for (int k = 0; k < 8; ++k) acc[n][k] = base[k];

#pragma unroll 1
            for (int d = 0; d < 64; d += 4) {
                float4 fv[4];
#pragma unroll
                for (int n = 0; n < 4; ++n)
                    fv[n] = f4[16 + (ch * 4 + n) * 16 + (d >> 2)];   // broadcast
#pragma unroll
                for (int dd = 0; dd < 4; ++dd) {
                    float4 w0 = sW4[(d + dd) * 64 + lane * 2];
                    float4 w1 = sW4[(d + dd) * 64 + lane * 2 + 1];
#pragma unroll
                    for (int n = 0; n < 4; ++n) {
                        float fe = (dd == 0) ? fv[n].x : (dd == 1) ? fv[n].y
                                 : (dd == 2) ? fv[n].z : fv[n].w;
                        acc[n][0] = fmaf(fe, w0.x, acc[n][0]);
                        acc[n][1] = fmaf(fe, w0.y, acc[n][1]);
                        acc[n][2] = fmaf(fe, w0.z, acc[n][2]);
                        acc[n][3] = fmaf(fe, w0.w, acc[n][3]);
                        acc[n][4] = fmaf(fe, w1.x, acc[n][4]);
                        acc[n][5] = fmaf(fe, w1.y, acc[n][5]);
                        acc[n][6] = fmaf(fe, w1.z, acc[n][6]);
                        acc[n][7] = fmaf(fe, w1.w, acc[n][7]);
                    }
                }
            }
#pragma unroll
            for (int n = 0; n < 4; ++n)
#pragma unroll
                for (int k = 0; k < 8; ++k)
                    vmax[k] = fmaxf(vmax[k], fmaxf(acc[n][k], 0.f));
        }

        // m = lane*8+k ; c = m>>2 ; r = m&3 ; y[(q*4+r)*64 + c]
#pragma unroll
        for (int r = 0; r < 4; ++r) {
            float2 v = make_float2(vmax[r], vmax[4 + r]);
            ((float2*)(y + (size_t)(q * 4 + r) * 64))[lane] = v;
        }
        __syncwarp();
    }
}

// ---------------------------------------------------------------------------
extern "C" void kernel_launch(void* const* d_in, const int* in_sizes, int n_in,
                              void* d_out, int out_size) {
    const float* x = (const float*)d_in[0];
    const float* W = (const float*)d_in[1];
    const float* b = (const float*)d_in[2];
    float* y = (float*)d_out;

    prep_kernel<<<N_PTS / 256, 256>>>(x);

    dim3 sgrid(N_PTS / QT, SPLIT);
    screen_kernel<<<sgrid, QT>>>();

    rerank_kernel<<<N_PTS / 8, 256>>>(x);

    cudaFuncSetAttribute(mlp_kernel,
                         cudaFuncAttributeMaxDynamicSharedMemorySize,
                         MLP_SMEM_FLOATS * sizeof(float));
    mlp_kernel<<<296, 256, MLP_SMEM_FLOATS * sizeof(float)>>>(x, W, b, y);
}